// round 1
// baseline (speedup 1.0000x reference)
#include <cuda_runtime.h>
#include <math.h>

#define NN 20000
#define EE 320000
#define ETOT 340000      // EE + NN self loops
#define ELN 100000

// ---------------- scratch (device globals; no allocation allowed) ----------
__device__ float g_xl1[NN*512];
__device__ float g_xr1[NN*512];
__device__ float g_z1 [NN*512];
__device__ float g_xl2[NN*128];
__device__ float g_xr2[NN*128];
__device__ float g_z2 [NN*128];
__device__ float g_elog1 [ETOT*4];
__device__ float g_alpha1[ETOT*4];
__device__ float g_elog2 [ETOT];
__device__ float g_alpha2[ETOT];
__device__ float g_nmax1[NN*4];
__device__ float g_nsum1[NN*4];
__device__ float g_nmax2[NN];
__device__ float g_nsum2[NN];
__device__ int   g_deg[NN];
__device__ int   g_rowptr[NN+1];
__device__ int   g_cursor[NN];
__device__ int   g_elist[ETOT];

__device__ __forceinline__ float gelu_t(float x){
  // JAX default gelu (approximate=True, tanh form)
  float u = 0.7978845608028654f*(x + 0.044715f*x*x*x);
  return 0.5f*x*(1.0f+tanhf(u));
}

// ---------------- CSR build --------------------------------------------------
__global__ void init_kernel(){
  int t=blockIdx.x*blockDim.x+threadIdx.x;
  if(t<NN){ g_deg[t]=0; g_cursor[t]=0; }
}

__global__ void count_kernel(const int* __restrict__ ei){
  int e=blockIdx.x*blockDim.x+threadIdx.x;
  if(e>=ETOT)return;
  int dst = (e<EE) ? ei[EE+e] : (e-EE);
  atomicAdd(&g_deg[dst],1);
}

__global__ void scan_kernel(){
  __shared__ int sums[1024];
  int tid=threadIdx.x;
  const int CH=(NN+1023)/1024;           // 20
  int start=tid*CH;
  int s=0;
  for(int i=0;i<CH;i++){int idx=start+i; if(idx<NN) s+=g_deg[idx];}
  sums[tid]=s; __syncthreads();
  for(int off=1;off<1024;off<<=1){
    int v=sums[tid];
    int add=(tid>=off)?sums[tid-off]:0;
    __syncthreads();
    sums[tid]=v+add;
    __syncthreads();
  }
  int run=(tid==0)?0:sums[tid-1];
  for(int i=0;i<CH;i++){
    int idx=start+i;
    if(idx<NN){ g_rowptr[idx]=run; run+=g_deg[idx]; }
  }
  if(tid==0) g_rowptr[NN]=sums[1023];
}

__global__ void scatter_kernel(const int* __restrict__ ei){
  int e=blockIdx.x*blockDim.x+threadIdx.x;
  if(e>=ETOT)return;
  int dst = (e<EE) ? ei[EE+e] : (e-EE);
  int pos=atomicAdd(&g_cursor[dst],1);
  g_elist[g_rowptr[dst]+pos]=e;
}

// ---------------- tiled fp32 GEMM: C = A[MxK] @ B[KxN] + bias ----------------
__global__ void gemm_bias(const float* __restrict__ A, const float* __restrict__ B,
                          const float* __restrict__ bias, float* __restrict__ C,
                          int M, int K, int Nc){
  __shared__ float As[16][68];   // padded
  __shared__ float Bs[16][64];
  int tid=threadIdx.x;
  int tx=tid&15, ty=tid>>4;
  int row0=blockIdx.y*64, col0=blockIdx.x*64;
  float acc[4][4]={};
  for(int k0=0;k0<K;k0+=16){
    for(int i=tid;i<64*16;i+=256){
      int r=i>>4, c=i&15;
      int gr=row0+r;
      As[c][r] = (gr<M)? A[(size_t)gr*K + k0 + c] : 0.f;
    }
    for(int i=tid;i<16*64;i+=256){
      int r=i>>6, c=i&63;
      Bs[r][c] = B[(size_t)(k0+r)*Nc + col0 + c];
    }
    __syncthreads();
    #pragma unroll
    for(int kk=0;kk<16;kk++){
      float a[4],b[4];
      #pragma unroll
      for(int i=0;i<4;i++) a[i]=As[kk][ty*4+i];
      #pragma unroll
      for(int j=0;j<4;j++) b[j]=Bs[kk][tx*4+j];
      #pragma unroll
      for(int i=0;i<4;i++)
        #pragma unroll
        for(int j=0;j<4;j++) acc[i][j]+=a[i]*b[j];
    }
    __syncthreads();
  }
  #pragma unroll
  for(int i=0;i<4;i++){
    int gr=row0+ty*4+i; if(gr>=M) continue;
    #pragma unroll
    for(int j=0;j<4;j++){
      int gc=col0+tx*4+j;
      C[(size_t)gr*Nc+gc]=acc[i][j]+bias[gc];
    }
  }
}

// ---------------- GATv2 layer 1 (H=4, C=128) --------------------------------
__global__ void edge_logits1_kernel(const int* __restrict__ ei, const float* __restrict__ att1){
  int e=blockIdx.x;                       // grid == ETOT
  int w=threadIdx.x>>5, lane=threadIdx.x&31;
  int src = (e<EE)? ei[e]    : (e-EE);
  int dst = (e<EE)? ei[EE+e] : (e-EE);
  const float* xs=g_xl1+(size_t)src*512+w*128;
  const float* xd=g_xr1+(size_t)dst*512+w*128;
  float acc=0.f;
  #pragma unroll
  for(int i=0;i<4;i++){
    int c=lane+32*i;
    float v=xs[c]+xd[c];
    v = v>0.f ? v : 0.2f*v;
    acc += v*att1[w*128+c];
  }
  #pragma unroll
  for(int o=16;o;o>>=1) acc+=__shfl_xor_sync(0xffffffffu,acc,o);
  if(lane==0) g_elog1[e*4+w]=acc;
}

__global__ void node_softmax1_kernel(){
  int t=blockIdx.x*blockDim.x+threadIdx.x;
  if(t>=NN*4)return;
  int node=t>>2, h=t&3;
  int b=g_rowptr[node], en=g_rowptr[node+1];
  float m=-1e30f;
  for(int i=b;i<en;i++) m=fmaxf(m, g_elog1[g_elist[i]*4+h]);
  float s=0.f;
  for(int i=b;i<en;i++) s+=expf(g_elog1[g_elist[i]*4+h]-m);
  g_nmax1[node*4+h]=m;
  g_nsum1[node*4+h]=s;
}

__global__ void alpha1_kernel(const int* __restrict__ ei){
  int t=blockIdx.x*blockDim.x+threadIdx.x;
  if(t>=ETOT*4)return;
  int e=t>>2, h=t&3;
  int dst=(e<EE)? ei[EE+e] : (e-EE);
  g_alpha1[t]=expf(g_elog1[t]-g_nmax1[dst*4+h])/g_nsum1[dst*4+h];
}

__global__ void aggregate1_kernel(const int* __restrict__ ei, const float* __restrict__ bias1){
  int node=blockIdx.x>>2, h=blockIdx.x&3, c=threadIdx.x;
  int b=g_rowptr[node], en=g_rowptr[node+1];
  float acc=0.f;
  for(int i=b;i<en;i++){
    int e=g_elist[i];
    int src=(e<EE)? ei[e] : (e-EE);
    acc += g_alpha1[e*4+h]*g_xl1[(size_t)src*512 + h*128 + c];
  }
  acc += bias1[h*128+c];
  g_z1[(size_t)node*512 + h*128 + c] = gelu_t(acc);   // gelu between layers
}

// ---------------- GATv2 layer 2 (H=1, C=128) --------------------------------
__global__ void edge_logits2_kernel(const int* __restrict__ ei, const float* __restrict__ att2){
  int e=blockIdx.x*4+(threadIdx.x>>5);
  if(e>=ETOT)return;
  int lane=threadIdx.x&31;
  int src=(e<EE)? ei[e]    : (e-EE);
  int dst=(e<EE)? ei[EE+e] : (e-EE);
  const float* xs=g_xl2+(size_t)src*128;
  const float* xd=g_xr2+(size_t)dst*128;
  float acc=0.f;
  #pragma unroll
  for(int i=0;i<4;i++){
    int c=lane+32*i;
    float v=xs[c]+xd[c];
    v = v>0.f ? v : 0.2f*v;
    acc += v*att2[c];
  }
  #pragma unroll
  for(int o=16;o;o>>=1) acc+=__shfl_xor_sync(0xffffffffu,acc,o);
  if(lane==0) g_elog2[e]=acc;
}

__global__ void node_softmax2_kernel(){
  int node=blockIdx.x*blockDim.x+threadIdx.x;
  if(node>=NN)return;
  int b=g_rowptr[node], en=g_rowptr[node+1];
  float m=-1e30f;
  for(int i=b;i<en;i++) m=fmaxf(m, g_elog2[g_elist[i]]);
  float s=0.f;
  for(int i=b;i<en;i++) s+=expf(g_elog2[g_elist[i]]-m);
  g_nmax2[node]=m;
  g_nsum2[node]=s;
}

__global__ void alpha2_kernel(const int* __restrict__ ei){
  int e=blockIdx.x*blockDim.x+threadIdx.x;
  if(e>=ETOT)return;
  int dst=(e<EE)? ei[EE+e] : (e-EE);
  g_alpha2[e]=expf(g_elog2[e]-g_nmax2[dst])/g_nsum2[dst];
}

__global__ void aggregate2_kernel(const int* __restrict__ ei, const float* __restrict__ bias2){
  int node=blockIdx.x, c=threadIdx.x;
  int b=g_rowptr[node], en=g_rowptr[node+1];
  float acc=0.f;
  for(int i=b;i<en;i++){
    int e=g_elist[i];
    int src=(e<EE)? ei[e] : (e-EE);
    acc += g_alpha2[e]*g_xl2[(size_t)src*128 + c];
  }
  g_z2[(size_t)node*128 + c] = acc + bias2[c];        // no gelu after layer 2
}

// ---------------- link decoder ----------------------------------------------
// smem: Wd1 (256x128=32768) + cat (8 edges x 256) + red (8 x 128)
#define DEC_SMEM_FLOATS (32768 + 2048 + 1024)
#define DEC_SMEM_BYTES  (DEC_SMEM_FLOATS*4)

__global__ void decoder_kernel(const int* __restrict__ eli, const float* __restrict__ Wd1,
                               const float* __restrict__ bd1, const float* __restrict__ Wd2,
                               const float* __restrict__ bd2, float* __restrict__ out){
  extern __shared__ float sm[];
  float* Ws  = sm;            // 32768
  float* cat = sm + 32768;    // 2048
  float* red = cat + 2048;    // 1024
  int tid=threadIdx.x;        // 256 threads
  int half=tid>>7, j=tid&127;
  for(int i=tid;i<32768;i+=256) Ws[i]=Wd1[i];
  float bj=bd1[j], w2=Wd2[j], b2=bd2[0];
  __syncthreads();

  for(int e0=blockIdx.x*8; e0<ELN; e0+=gridDim.x*8){
    #pragma unroll
    for(int m=0;m<8;m++){
      int e=e0+m;
      if(e<ELN){
        int idx = (tid<128) ? eli[e] : eli[ELN+e];
        cat[m*256+tid] = g_z2[(size_t)idx*128 + (tid&127)];
      }
    }
    __syncthreads();
    float a0=bj,a1=bj,a2=bj,a3=bj;
    const float* c0=cat + half*1024;
    #pragma unroll 4
    for(int k=0;k<256;k++){
      float w=Ws[k*128+j];
      a0 += c0[k      ]*w;
      a1 += c0[256+k  ]*w;
      a2 += c0[512+k  ]*w;
      a3 += c0[768+k  ]*w;
    }
    red[(half*4+0)*128+j]=gelu_t(a0)*w2;
    red[(half*4+1)*128+j]=gelu_t(a1)*w2;
    red[(half*4+2)*128+j]=gelu_t(a2)*w2;
    red[(half*4+3)*128+j]=gelu_t(a3)*w2;
    __syncthreads();
    for(int s=64;s>=1;s>>=1){
      if(j<s){
        #pragma unroll
        for(int m=0;m<4;m++) red[(half*4+m)*128+j]+=red[(half*4+m)*128+j+s];
      }
      __syncthreads();
    }
    if(tid<8 && (e0+tid)<ELN) out[e0+tid]=red[tid*128]+b2;
    __syncthreads();
  }
}

// ---------------- launch -----------------------------------------------------
extern "C" void kernel_launch(void* const* d_in, const int* in_sizes, int n_in,
                              void* d_out, int out_size){
  const float* x    =(const float*)d_in[0];
  const int*   ei   =(const int*  )d_in[1];
  const int*   eli  =(const int*  )d_in[2];
  const float* Wl1  =(const float*)d_in[3];
  const float* bl1  =(const float*)d_in[4];
  const float* Wr1  =(const float*)d_in[5];
  const float* br1  =(const float*)d_in[6];
  const float* att1 =(const float*)d_in[7];
  const float* bias1=(const float*)d_in[8];
  const float* Wl2  =(const float*)d_in[9];
  const float* bl2  =(const float*)d_in[10];
  const float* Wr2  =(const float*)d_in[11];
  const float* br2  =(const float*)d_in[12];
  const float* att2 =(const float*)d_in[13];
  const float* bias2=(const float*)d_in[14];
  const float* Wd1  =(const float*)d_in[15];
  const float* bd1  =(const float*)d_in[16];
  const float* Wd2  =(const float*)d_in[17];
  const float* bd2  =(const float*)d_in[18];
  float* out=(float*)d_out;

  float *p_xl1,*p_xr1,*p_z1,*p_xl2,*p_xr2;
  cudaGetSymbolAddress((void**)&p_xl1, g_xl1);
  cudaGetSymbolAddress((void**)&p_xr1, g_xr1);
  cudaGetSymbolAddress((void**)&p_z1 , g_z1 );
  cudaGetSymbolAddress((void**)&p_xl2, g_xl2);
  cudaGetSymbolAddress((void**)&p_xr2, g_xr2);

  // CSR build (independent of GEMMs, same stream)
  init_kernel   <<<(NN+255)/256,256>>>();
  count_kernel  <<<(ETOT+255)/256,256>>>(ei);
  scan_kernel   <<<1,1024>>>();
  scatter_kernel<<<(ETOT+255)/256,256>>>(ei);

  // layer-1 node transforms
  gemm_bias<<<dim3(512/64,(NN+63)/64),256>>>(x, Wl1, bl1, p_xl1, NN, 256, 512);
  gemm_bias<<<dim3(512/64,(NN+63)/64),256>>>(x, Wr1, br1, p_xr1, NN, 256, 512);

  // layer-1 attention
  edge_logits1_kernel <<<ETOT,128>>>(ei, att1);
  node_softmax1_kernel<<<(NN*4+255)/256,256>>>();
  alpha1_kernel       <<<(ETOT*4+255)/256,256>>>(ei);
  aggregate1_kernel   <<<NN*4,128>>>(ei, bias1);

  // layer-2 node transforms (input = gelu'd z1)
  gemm_bias<<<dim3(128/64,(NN+63)/64),256>>>(p_z1, Wl2, bl2, p_xl2, NN, 512, 128);
  gemm_bias<<<dim3(128/64,(NN+63)/64),256>>>(p_z1, Wr2, br2, p_xr2, NN, 512, 128);

  // layer-2 attention
  edge_logits2_kernel <<<(ETOT+3)/4,128>>>(ei, att2);
  node_softmax2_kernel<<<(NN+255)/256,256>>>();
  alpha2_kernel       <<<(ETOT+255)/256,256>>>(ei);
  aggregate2_kernel   <<<NN,128>>>(ei, bias2);

  // decoder
  cudaFuncSetAttribute(decoder_kernel, cudaFuncAttributeMaxDynamicSharedMemorySize, DEC_SMEM_BYTES);
  decoder_kernel<<<148,256,DEC_SMEM_BYTES>>>(eli, Wd1, bd1, Wd2, bd2, out);
}

// round 2
// speedup vs baseline: 1.8428x; 1.8428x over previous
#include <cuda_runtime.h>
#include <mma.h>
#include <math.h>

using namespace nvcuda;

#define NN 20000
#define EE 320000
#define ETOT 340000      // EE + NN self loops
#define ELN 100000

// ---------------- scratch (device globals; no allocation allowed) ----------
__device__ float g_xl1[NN*512];
__device__ float g_xr1[NN*512];
__device__ float g_z1 [NN*512];
__device__ float g_xl2[NN*128];
__device__ float g_xr2[NN*128];
__device__ float g_z2 [NN*128];
__device__ float g_h  [ELN*128];
__device__ float g_elog1 [ETOT*4];
__device__ float g_alpha1[ETOT*4];
__device__ float g_elog2 [ETOT];
__device__ float g_alpha2[ETOT];
__device__ float g_nmax1[NN*4];
__device__ float g_nsum1[NN*4];
__device__ float g_nmax2[NN];
__device__ float g_nsum2[NN];
__device__ int   g_deg[NN];
__device__ int   g_rowptr[NN+1];
__device__ int   g_cursor[NN];
__device__ int   g_elist[ETOT];

__device__ __forceinline__ float gelu_t(float x){
  // JAX default gelu (approximate=True, tanh form)
  float u = 0.7978845608028654f*(x + 0.044715f*x*x*x);
  return 0.5f*x*(1.0f+tanhf(u));
}

// ---------------- CSR build --------------------------------------------------
__global__ void init_kernel(){
  int t=blockIdx.x*blockDim.x+threadIdx.x;
  if(t<NN){ g_deg[t]=0; g_cursor[t]=0; }
}

__global__ void count_kernel(const int* __restrict__ ei){
  int e=blockIdx.x*blockDim.x+threadIdx.x;
  if(e>=ETOT)return;
  int dst = (e<EE) ? ei[EE+e] : (e-EE);
  atomicAdd(&g_deg[dst],1);
}

__global__ void scan_kernel(){
  __shared__ int sums[1024];
  int tid=threadIdx.x;
  const int CH=(NN+1023)/1024;           // 20
  int start=tid*CH;
  int s=0;
  for(int i=0;i<CH;i++){int idx=start+i; if(idx<NN) s+=g_deg[idx];}
  sums[tid]=s; __syncthreads();
  for(int off=1;off<1024;off<<=1){
    int v=sums[tid];
    int add=(tid>=off)?sums[tid-off]:0;
    __syncthreads();
    sums[tid]=v+add;
    __syncthreads();
  }
  int run=(tid==0)?0:sums[tid-1];
  for(int i=0;i<CH;i++){
    int idx=start+i;
    if(idx<NN){ g_rowptr[idx]=run; run+=g_deg[idx]; }
  }
  if(tid==0) g_rowptr[NN]=sums[1023];
}

__global__ void scatter_kernel(const int* __restrict__ ei){
  int e=blockIdx.x*blockDim.x+threadIdx.x;
  if(e>=ETOT)return;
  int dst = (e<EE) ? ei[EE+e] : (e-EE);
  int pos=atomicAdd(&g_cursor[dst],1);
  g_elist[g_rowptr[dst]+pos]=e;
}

// ---------------- TF32 WMMA GEMM ---------------------------------------------
// Block tile 128x128, BK=16, 8 warps in 4x2, each warp 32x64 (2x4 wmma tiles).
// Computes TWO gemms sharing A (blockIdx.z selects B/bias/C): C_z = A @ B_z + bias_z.
#define BM 128
#define BN 128
#define BK 16

__global__ void wmma_gemm2(const float* __restrict__ A,
                           const float* __restrict__ B1, const float* __restrict__ bias1_,
                           float* __restrict__ C1,
                           const float* __restrict__ B2, const float* __restrict__ bias2_,
                           float* __restrict__ C2,
                           int M, int K, int N){
  const float* B    = blockIdx.z ? B2 : B1;
  const float* bias = blockIdx.z ? bias2_ : bias1_;
  float*       C    = blockIdx.z ? C2 : C1;

  __shared__ float As[BM][BK+4];
  __shared__ float Bs[BK][BN+4];
  __shared__ float St[8][16][20];

  int tid=threadIdx.x;
  int warp=tid>>5, lane=tid&31;
  int wm=warp>>1, wn=warp&1;
  int row0=blockIdx.y*BM, col0=blockIdx.x*BN;

  wmma::fragment<wmma::accumulator,16,16,8,float> acc[2][4];
  #pragma unroll
  for(int i=0;i<2;i++)
    #pragma unroll
    for(int j=0;j<4;j++) wmma::fill_fragment(acc[i][j],0.f);

  for(int k0=0;k0<K;k0+=BK){
    #pragma unroll
    for(int it=0;it<2;it++){
      int i=tid+256*it;
      int r=i>>2, c4=(i&3)*4;
      float4 v={0.f,0.f,0.f,0.f};
      int gr=row0+r;
      if(gr<M) v=*(const float4*)&A[(size_t)gr*K + k0 + c4];
      As[r][c4+0]=wmma::__float_to_tf32(v.x);
      As[r][c4+1]=wmma::__float_to_tf32(v.y);
      As[r][c4+2]=wmma::__float_to_tf32(v.z);
      As[r][c4+3]=wmma::__float_to_tf32(v.w);
    }
    #pragma unroll
    for(int it=0;it<2;it++){
      int i=tid+256*it;
      int r=i>>5, c4=(i&31)*4;
      float4 v=*(const float4*)&B[(size_t)(k0+r)*N + col0 + c4];
      Bs[r][c4+0]=wmma::__float_to_tf32(v.x);
      Bs[r][c4+1]=wmma::__float_to_tf32(v.y);
      Bs[r][c4+2]=wmma::__float_to_tf32(v.z);
      Bs[r][c4+3]=wmma::__float_to_tf32(v.w);
    }
    __syncthreads();
    #pragma unroll
    for(int ks=0;ks<BK;ks+=8){
      wmma::fragment<wmma::matrix_a,16,16,8,wmma::precision::tf32,wmma::row_major> af[2];
      wmma::fragment<wmma::matrix_b,16,16,8,wmma::precision::tf32,wmma::row_major> bf[4];
      #pragma unroll
      for(int i=0;i<2;i++) wmma::load_matrix_sync(af[i], &As[wm*32+i*16][ks], BK+4);
      #pragma unroll
      for(int j=0;j<4;j++) wmma::load_matrix_sync(bf[j], &Bs[ks][wn*64+j*16], BN+4);
      #pragma unroll
      for(int i=0;i<2;i++)
        #pragma unroll
        for(int j=0;j<4;j++) wmma::mma_sync(acc[i][j],af[i],bf[j],acc[i][j]);
    }
    __syncthreads();
  }
  // epilogue: per-warp staging, bias
  #pragma unroll
  for(int i=0;i<2;i++)
    #pragma unroll
    for(int j=0;j<4;j++){
      wmma::store_matrix_sync(&St[warp][0][0], acc[i][j], 20, wmma::mem_row_major);
      __syncwarp();
      int r0=row0+wm*32+i*16, c0=col0+wn*64+j*16;
      #pragma unroll
      for(int t=lane;t<256;t+=32){
        int rr=t>>4, cc=t&15;
        int gr=r0+rr, gc=c0+cc;
        if(gr<M) C[(size_t)gr*N+gc]=St[warp][rr][cc]+bias[gc];
      }
      __syncwarp();
    }
}

// Decoder GEMM: H[ELN x 128] = gelu( cat(z2[eli0], z2[eli1]) @ Wd1 + bd1 )
// A-tile gather fused: K=256, first 128 cols from z2[eli0[r]], last from z2[eli1[r]].
__global__ void wmma_gemm_dec(const int* __restrict__ eli,
                              const float* __restrict__ B,   // Wd1 [256x128]
                              const float* __restrict__ bias,
                              float* __restrict__ H){
  const int K=256, N=128;
  __shared__ float As[BM][BK+4];
  __shared__ float Bs[BK][BN+4];
  __shared__ float St[8][16][20];

  int tid=threadIdx.x;
  int warp=tid>>5, lane=tid&31;
  int wm=warp>>1, wn=warp&1;
  int row0=blockIdx.y*BM;

  wmma::fragment<wmma::accumulator,16,16,8,float> acc[2][4];
  #pragma unroll
  for(int i=0;i<2;i++)
    #pragma unroll
    for(int j=0;j<4;j++) wmma::fill_fragment(acc[i][j],0.f);

  for(int k0=0;k0<K;k0+=BK){
    const int* idxp = (k0<128) ? eli : (eli+ELN);
    int koff = (k0<128) ? k0 : (k0-128);
    #pragma unroll
    for(int it=0;it<2;it++){
      int i=tid+256*it;
      int r=i>>2, c4=(i&3)*4;
      float4 v={0.f,0.f,0.f,0.f};
      int gr=row0+r;
      if(gr<ELN){
        int node=idxp[gr];
        v=*(const float4*)&g_z2[(size_t)node*128 + koff + c4];
      }
      As[r][c4+0]=wmma::__float_to_tf32(v.x);
      As[r][c4+1]=wmma::__float_to_tf32(v.y);
      As[r][c4+2]=wmma::__float_to_tf32(v.z);
      As[r][c4+3]=wmma::__float_to_tf32(v.w);
    }
    #pragma unroll
    for(int it=0;it<2;it++){
      int i=tid+256*it;
      int r=i>>5, c4=(i&31)*4;
      float4 v=*(const float4*)&B[(size_t)(k0+r)*N + c4];
      Bs[r][c4+0]=wmma::__float_to_tf32(v.x);
      Bs[r][c4+1]=wmma::__float_to_tf32(v.y);
      Bs[r][c4+2]=wmma::__float_to_tf32(v.z);
      Bs[r][c4+3]=wmma::__float_to_tf32(v.w);
    }
    __syncthreads();
    #pragma unroll
    for(int ks=0;ks<BK;ks+=8){
      wmma::fragment<wmma::matrix_a,16,16,8,wmma::precision::tf32,wmma::row_major> af[2];
      wmma::fragment<wmma::matrix_b,16,16,8,wmma::precision::tf32,wmma::row_major> bf[4];
      #pragma unroll
      for(int i=0;i<2;i++) wmma::load_matrix_sync(af[i], &As[wm*32+i*16][ks], BK+4);
      #pragma unroll
      for(int j=0;j<4;j++) wmma::load_matrix_sync(bf[j], &Bs[ks][wn*64+j*16], BN+4);
      #pragma unroll
      for(int i=0;i<2;i++)
        #pragma unroll
        for(int j=0;j<4;j++) wmma::mma_sync(acc[i][j],af[i],bf[j],acc[i][j]);
    }
    __syncthreads();
  }
  #pragma unroll
  for(int i=0;i<2;i++)
    #pragma unroll
    for(int j=0;j<4;j++){
      wmma::store_matrix_sync(&St[warp][0][0], acc[i][j], 20, wmma::mem_row_major);
      __syncwarp();
      int r0=row0+wm*32+i*16, c0=wn*64+j*16;
      #pragma unroll
      for(int t=lane;t<256;t+=32){
        int rr=t>>4, cc=t&15;
        int gr=r0+rr, gc=c0+cc;
        if(gr<ELN) g_h[(size_t)gr*128+gc]=gelu_t(St[warp][rr][cc]+bias[gc]);
      }
      __syncwarp();
    }
}

// ---------------- GATv2 layer 1 (H=4, C=128) --------------------------------
__global__ void edge_logits1_kernel(const int* __restrict__ ei, const float* __restrict__ att1){
  int e=blockIdx.x;                       // grid == ETOT
  int w=threadIdx.x>>5, lane=threadIdx.x&31;
  int src = (e<EE)? ei[e]    : (e-EE);
  int dst = (e<EE)? ei[EE+e] : (e-EE);
  const float* xs=g_xl1+(size_t)src*512+w*128;
  const float* xd=g_xr1+(size_t)dst*512+w*128;
  float acc=0.f;
  #pragma unroll
  for(int i=0;i<4;i++){
    int c=lane+32*i;
    float v=xs[c]+xd[c];
    v = v>0.f ? v : 0.2f*v;
    acc += v*att1[w*128+c];
  }
  #pragma unroll
  for(int o=16;o;o>>=1) acc+=__shfl_xor_sync(0xffffffffu,acc,o);
  if(lane==0) g_elog1[e*4+w]=acc;
}

__global__ void node_softmax1_kernel(){
  int t=blockIdx.x*blockDim.x+threadIdx.x;
  if(t>=NN*4)return;
  int node=t>>2, h=t&3;
  int b=g_rowptr[node], en=g_rowptr[node+1];
  float m=-1e30f;
  for(int i=b;i<en;i++) m=fmaxf(m, g_elog1[g_elist[i]*4+h]);
  float s=0.f;
  for(int i=b;i<en;i++) s+=expf(g_elog1[g_elist[i]*4+h]-m);
  g_nmax1[node*4+h]=m;
  g_nsum1[node*4+h]=s;
}

__global__ void alpha1_kernel(const int* __restrict__ ei){
  int t=blockIdx.x*blockDim.x+threadIdx.x;
  if(t>=ETOT*4)return;
  int e=t>>2, h=t&3;
  int dst=(e<EE)? ei[EE+e] : (e-EE);
  g_alpha1[t]=expf(g_elog1[t]-g_nmax1[dst*4+h])/g_nsum1[dst*4+h];
}

__global__ void aggregate1_kernel(const int* __restrict__ ei, const float* __restrict__ bias1){
  int node=blockIdx.x>>2, h=blockIdx.x&3, c=threadIdx.x;
  int b=g_rowptr[node], en=g_rowptr[node+1];
  float acc=0.f;
  for(int i=b;i<en;i++){
    int e=g_elist[i];
    int src=(e<EE)? ei[e] : (e-EE);
    acc += g_alpha1[e*4+h]*g_xl1[(size_t)src*512 + h*128 + c];
  }
  acc += bias1[h*128+c];
  g_z1[(size_t)node*512 + h*128 + c] = gelu_t(acc);   // gelu between layers
}

// ---------------- GATv2 layer 2 (H=1, C=128) --------------------------------
__global__ void edge_logits2_kernel(const int* __restrict__ ei, const float* __restrict__ att2){
  int e=blockIdx.x*4+(threadIdx.x>>5);
  if(e>=ETOT)return;
  int lane=threadIdx.x&31;
  int src=(e<EE)? ei[e]    : (e-EE);
  int dst=(e<EE)? ei[EE+e] : (e-EE);
  const float* xs=g_xl2+(size_t)src*128;
  const float* xd=g_xr2+(size_t)dst*128;
  float acc=0.f;
  #pragma unroll
  for(int i=0;i<4;i++){
    int c=lane+32*i;
    float v=xs[c]+xd[c];
    v = v>0.f ? v : 0.2f*v;
    acc += v*att2[c];
  }
  #pragma unroll
  for(int o=16;o;o>>=1) acc+=__shfl_xor_sync(0xffffffffu,acc,o);
  if(lane==0) g_elog2[e]=acc;
}

__global__ void node_softmax2_kernel(){
  int node=blockIdx.x*blockDim.x+threadIdx.x;
  if(node>=NN)return;
  int b=g_rowptr[node], en=g_rowptr[node+1];
  float m=-1e30f;
  for(int i=b;i<en;i++) m=fmaxf(m, g_elog2[g_elist[i]]);
  float s=0.f;
  for(int i=b;i<en;i++) s+=expf(g_elog2[g_elist[i]]-m);
  g_nmax2[node]=m;
  g_nsum2[node]=s;
}

__global__ void alpha2_kernel(const int* __restrict__ ei){
  int e=blockIdx.x*blockDim.x+threadIdx.x;
  if(e>=ETOT)return;
  int dst=(e<EE)? ei[EE+e] : (e-EE);
  g_alpha2[e]=expf(g_elog2[e]-g_nmax2[dst])/g_nsum2[dst];
}

__global__ void aggregate2_kernel(const int* __restrict__ ei, const float* __restrict__ bias2){
  int node=blockIdx.x, c=threadIdx.x;
  int b=g_rowptr[node], en=g_rowptr[node+1];
  float acc=0.f;
  for(int i=b;i<en;i++){
    int e=g_elist[i];
    int src=(e<EE)? ei[e] : (e-EE);
    acc += g_alpha2[e]*g_xl2[(size_t)src*128 + c];
  }
  g_z2[(size_t)node*128 + c] = acc + bias2[c];        // no gelu after layer 2
}

// ---------------- decoder output: out[e] = h[e] . Wd2 + b2 -------------------
__global__ void dec_out_kernel(const float* __restrict__ Wd2, const float* __restrict__ bd2,
                               float* __restrict__ out){
  int warp=threadIdx.x>>5, lane=threadIdx.x&31;
  int e=blockIdx.x*8+warp;
  if(e>=ELN) return;
  const float* h=g_h+(size_t)e*128;
  float acc=0.f;
  #pragma unroll
  for(int i=0;i<4;i++){
    int c=lane+32*i;
    acc += h[c]*Wd2[c];
  }
  #pragma unroll
  for(int o=16;o;o>>=1) acc+=__shfl_xor_sync(0xffffffffu,acc,o);
  if(lane==0) out[e]=acc+bd2[0];
}

// ---------------- launch -----------------------------------------------------
extern "C" void kernel_launch(void* const* d_in, const int* in_sizes, int n_in,
                              void* d_out, int out_size){
  const float* x    =(const float*)d_in[0];
  const int*   ei   =(const int*  )d_in[1];
  const int*   eli  =(const int*  )d_in[2];
  const float* Wl1  =(const float*)d_in[3];
  const float* bl1  =(const float*)d_in[4];
  const float* Wr1  =(const float*)d_in[5];
  const float* br1  =(const float*)d_in[6];
  const float* att1 =(const float*)d_in[7];
  const float* bias1=(const float*)d_in[8];
  const float* Wl2  =(const float*)d_in[9];
  const float* bl2  =(const float*)d_in[10];
  const float* Wr2  =(const float*)d_in[11];
  const float* br2  =(const float*)d_in[12];
  const float* att2 =(const float*)d_in[13];
  const float* bias2=(const float*)d_in[14];
  const float* Wd1  =(const float*)d_in[15];
  const float* bd1  =(const float*)d_in[16];
  const float* Wd2  =(const float*)d_in[17];
  const float* bd2  =(const float*)d_in[18];
  float* out=(float*)d_out;

  float *p_xl1,*p_xr1,*p_z1,*p_xl2,*p_xr2;
  cudaGetSymbolAddress((void**)&p_xl1, g_xl1);
  cudaGetSymbolAddress((void**)&p_xr1, g_xr1);
  cudaGetSymbolAddress((void**)&p_z1 , g_z1 );
  cudaGetSymbolAddress((void**)&p_xl2, g_xl2);
  cudaGetSymbolAddress((void**)&p_xr2, g_xr2);

  // CSR build
  init_kernel   <<<(NN+255)/256,256>>>();
  count_kernel  <<<(ETOT+255)/256,256>>>(ei);
  scan_kernel   <<<1,1024>>>();
  scatter_kernel<<<(ETOT+255)/256,256>>>(ei);

  // layer-1 node transforms: xl1 = x@Wl1+bl1, xr1 = x@Wr1+br1 (shared A)
  wmma_gemm2<<<dim3(512/128,(NN+127)/128,2),256>>>(x, Wl1, bl1, p_xl1, Wr1, br1, p_xr1,
                                                   NN, 256, 512);

  // layer-1 attention
  edge_logits1_kernel <<<ETOT,128>>>(ei, att1);
  node_softmax1_kernel<<<(NN*4+255)/256,256>>>();
  alpha1_kernel       <<<(ETOT*4+255)/256,256>>>(ei);
  aggregate1_kernel   <<<NN*4,128>>>(ei, bias1);

  // layer-2 node transforms
  wmma_gemm2<<<dim3(1,(NN+127)/128,2),256>>>(p_z1, Wl2, bl2, p_xl2, Wr2, br2, p_xr2,
                                             NN, 512, 128);

  // layer-2 attention
  edge_logits2_kernel <<<(ETOT+3)/4,128>>>(ei, att2);
  node_softmax2_kernel<<<(NN+255)/256,256>>>();
  alpha2_kernel       <<<(ETOT+255)/256,256>>>(ei);
  aggregate2_kernel   <<<NN,128>>>(ei, bias2);

  // decoder: gather-fused GEMM + gelu, then 128-dot
  wmma_gemm_dec<<<dim3(1,(ELN+127)/128),256>>>(eli, Wd1, bd1, nullptr);
  dec_out_kernel<<<(ELN+7)/8,256>>>(Wd2, bd2, out);
}

// round 3
// speedup vs baseline: 2.4845x; 1.3482x over previous
#include <cuda_runtime.h>
#include <mma.h>
#include <math.h>

using namespace nvcuda;

#define NN 20000
#define EE 320000
#define ETOT 340000      // EE + NN self loops
#define ELN 100000

// ---------------- scratch (device globals; no allocation allowed) ----------
__device__ float g_xl1[NN*512];
__device__ float g_xr1[NN*512];
__device__ float g_z1 [NN*512];
__device__ float g_xl2[NN*128];
__device__ float g_xr2[NN*128];
__device__ float g_z2 [NN*128];
__device__ float g_h  [ELN*128];
__device__ int   g_deg[NN];
__device__ int   g_rowptr[NN+1];
__device__ int   g_cursor[NN];
__device__ int   g_elist[ETOT];

__device__ __forceinline__ float gelu_t(float x){
  // JAX default gelu (approximate=True, tanh form)
  float u = 0.7978845608028654f*(x + 0.044715f*x*x*x);
  return 0.5f*x*(1.0f+tanhf(u));
}

// ---------------- CSR build --------------------------------------------------
__global__ void init_kernel(){
  int t=blockIdx.x*blockDim.x+threadIdx.x;
  if(t<NN){ g_deg[t]=0; g_cursor[t]=0; }
}

__global__ void count_kernel(const int* __restrict__ ei){
  int e=blockIdx.x*blockDim.x+threadIdx.x;
  if(e>=ETOT)return;
  int dst = (e<EE) ? ei[EE+e] : (e-EE);
  atomicAdd(&g_deg[dst],1);
}

__global__ void scan_kernel(){
  __shared__ int sums[1024];
  int tid=threadIdx.x;
  const int CH=(NN+1023)/1024;           // 20
  int start=tid*CH;
  int s=0;
  for(int i=0;i<CH;i++){int idx=start+i; if(idx<NN) s+=g_deg[idx];}
  sums[tid]=s; __syncthreads();
  for(int off=1;off<1024;off<<=1){
    int v=sums[tid];
    int add=(tid>=off)?sums[tid-off]:0;
    __syncthreads();
    sums[tid]=v+add;
    __syncthreads();
  }
  int run=(tid==0)?0:sums[tid-1];
  for(int i=0;i<CH;i++){
    int idx=start+i;
    if(idx<NN){ g_rowptr[idx]=run; run+=g_deg[idx]; }
  }
  if(tid==0) g_rowptr[NN]=sums[1023];
}

__global__ void scatter_kernel(const int* __restrict__ ei){
  int e=blockIdx.x*blockDim.x+threadIdx.x;
  if(e>=ETOT)return;
  int dst = (e<EE) ? ei[EE+e] : (e-EE);
  int pos=atomicAdd(&g_cursor[dst],1);
  g_elist[g_rowptr[dst]+pos]=e;
}

// ---------------- TF32 WMMA GEMM ---------------------------------------------
// Block tile 128x128, BK=16, 8 warps in 4x2, each warp 32x64 (2x4 wmma tiles).
// Computes TWO gemms sharing A (blockIdx.z selects B/bias/C): C_z = A @ B_z + bias_z.
#define BM 128
#define BN 128
#define BK 16

__global__ void wmma_gemm2(const float* __restrict__ A,
                           const float* __restrict__ B1, const float* __restrict__ bias1_,
                           float* __restrict__ C1,
                           const float* __restrict__ B2, const float* __restrict__ bias2_,
                           float* __restrict__ C2,
                           int M, int K, int N){
  const float* B    = blockIdx.z ? B2 : B1;
  const float* bias = blockIdx.z ? bias2_ : bias1_;
  float*       C    = blockIdx.z ? C2 : C1;

  __shared__ float As[BM][BK+4];
  __shared__ float Bs[BK][BN+4];
  __shared__ float St[8][16][20];

  int tid=threadIdx.x;
  int warp=tid>>5, lane=tid&31;
  int wm=warp>>1, wn=warp&1;
  int row0=blockIdx.y*BM, col0=blockIdx.x*BN;

  wmma::fragment<wmma::accumulator,16,16,8,float> acc[2][4];
  #pragma unroll
  for(int i=0;i<2;i++)
    #pragma unroll
    for(int j=0;j<4;j++) wmma::fill_fragment(acc[i][j],0.f);

  for(int k0=0;k0<K;k0+=BK){
    #pragma unroll
    for(int it=0;it<2;it++){
      int i=tid+256*it;
      int r=i>>2, c4=(i&3)*4;
      float4 v={0.f,0.f,0.f,0.f};
      int gr=row0+r;
      if(gr<M) v=*(const float4*)&A[(size_t)gr*K + k0 + c4];
      As[r][c4+0]=wmma::__float_to_tf32(v.x);
      As[r][c4+1]=wmma::__float_to_tf32(v.y);
      As[r][c4+2]=wmma::__float_to_tf32(v.z);
      As[r][c4+3]=wmma::__float_to_tf32(v.w);
    }
    #pragma unroll
    for(int it=0;it<2;it++){
      int i=tid+256*it;
      int r=i>>5, c4=(i&31)*4;
      float4 v=*(const float4*)&B[(size_t)(k0+r)*N + col0 + c4];
      Bs[r][c4+0]=wmma::__float_to_tf32(v.x);
      Bs[r][c4+1]=wmma::__float_to_tf32(v.y);
      Bs[r][c4+2]=wmma::__float_to_tf32(v.z);
      Bs[r][c4+3]=wmma::__float_to_tf32(v.w);
    }
    __syncthreads();
    #pragma unroll
    for(int ks=0;ks<BK;ks+=8){
      wmma::fragment<wmma::matrix_a,16,16,8,wmma::precision::tf32,wmma::row_major> af[2];
      wmma::fragment<wmma::matrix_b,16,16,8,wmma::precision::tf32,wmma::row_major> bf[4];
      #pragma unroll
      for(int i=0;i<2;i++) wmma::load_matrix_sync(af[i], &As[wm*32+i*16][ks], BK+4);
      #pragma unroll
      for(int j=0;j<4;j++) wmma::load_matrix_sync(bf[j], &Bs[ks][wn*64+j*16], BN+4);
      #pragma unroll
      for(int i=0;i<2;i++)
        #pragma unroll
        for(int j=0;j<4;j++) wmma::mma_sync(acc[i][j],af[i],bf[j],acc[i][j]);
    }
    __syncthreads();
  }
  // epilogue: per-warp staging, bias
  #pragma unroll
  for(int i=0;i<2;i++)
    #pragma unroll
    for(int j=0;j<4;j++){
      wmma::store_matrix_sync(&St[warp][0][0], acc[i][j], 20, wmma::mem_row_major);
      __syncwarp();
      int r0=row0+wm*32+i*16, c0=col0+wn*64+j*16;
      #pragma unroll
      for(int t=lane;t<256;t+=32){
        int rr=t>>4, cc=t&15;
        int gr=r0+rr, gc=c0+cc;
        if(gr<M) C[(size_t)gr*N+gc]=St[warp][rr][cc]+bias[gc];
      }
      __syncwarp();
    }
}

// Decoder GEMM: H[ELN x 128] = gelu( cat(z2[eli0], z2[eli1]) @ Wd1 + bd1 )
__global__ void wmma_gemm_dec(const int* __restrict__ eli,
                              const float* __restrict__ B,   // Wd1 [256x128]
                              const float* __restrict__ bias){
  const int K=256, N=128;
  __shared__ float As[BM][BK+4];
  __shared__ float Bs[BK][BN+4];
  __shared__ float St[8][16][20];

  int tid=threadIdx.x;
  int warp=tid>>5, lane=tid&31;
  int wm=warp>>1, wn=warp&1;
  int row0=blockIdx.y*BM;

  wmma::fragment<wmma::accumulator,16,16,8,float> acc[2][4];
  #pragma unroll
  for(int i=0;i<2;i++)
    #pragma unroll
    for(int j=0;j<4;j++) wmma::fill_fragment(acc[i][j],0.f);

  for(int k0=0;k0<K;k0+=BK){
    const int* idxp = (k0<128) ? eli : (eli+ELN);
    int koff = (k0<128) ? k0 : (k0-128);
    #pragma unroll
    for(int it=0;it<2;it++){
      int i=tid+256*it;
      int r=i>>2, c4=(i&3)*4;
      float4 v={0.f,0.f,0.f,0.f};
      int gr=row0+r;
      if(gr<ELN){
        int node=idxp[gr];
        v=*(const float4*)&g_z2[(size_t)node*128 + koff + c4];
      }
      As[r][c4+0]=wmma::__float_to_tf32(v.x);
      As[r][c4+1]=wmma::__float_to_tf32(v.y);
      As[r][c4+2]=wmma::__float_to_tf32(v.z);
      As[r][c4+3]=wmma::__float_to_tf32(v.w);
    }
    #pragma unroll
    for(int it=0;it<2;it++){
      int i=tid+256*it;
      int r=i>>5, c4=(i&31)*4;
      float4 v=*(const float4*)&B[(size_t)(k0+r)*N + c4];
      Bs[r][c4+0]=wmma::__float_to_tf32(v.x);
      Bs[r][c4+1]=wmma::__float_to_tf32(v.y);
      Bs[r][c4+2]=wmma::__float_to_tf32(v.z);
      Bs[r][c4+3]=wmma::__float_to_tf32(v.w);
    }
    __syncthreads();
    #pragma unroll
    for(int ks=0;ks<BK;ks+=8){
      wmma::fragment<wmma::matrix_a,16,16,8,wmma::precision::tf32,wmma::row_major> af[2];
      wmma::fragment<wmma::matrix_b,16,16,8,wmma::precision::tf32,wmma::row_major> bf[4];
      #pragma unroll
      for(int i=0;i<2;i++) wmma::load_matrix_sync(af[i], &As[wm*32+i*16][ks], BK+4);
      #pragma unroll
      for(int j=0;j<4;j++) wmma::load_matrix_sync(bf[j], &Bs[ks][wn*64+j*16], BN+4);
      #pragma unroll
      for(int i=0;i<2;i++)
        #pragma unroll
        for(int j=0;j<4;j++) wmma::mma_sync(acc[i][j],af[i],bf[j],acc[i][j]);
    }
    __syncthreads();
  }
  #pragma unroll
  for(int i=0;i<2;i++)
    #pragma unroll
    for(int j=0;j<4;j++){
      wmma::store_matrix_sync(&St[warp][0][0], acc[i][j], 20, wmma::mem_row_major);
      __syncwarp();
      int r0=row0+wm*32+i*16, c0=wn*64+j*16;
      #pragma unroll
      for(int t=lane;t<256;t+=32){
        int rr=t>>4, cc=t&15;
        int gr=r0+rr, gc=c0+cc;
        if(gr<ELN) g_h[(size_t)gr*128+gc]=gelu_t(St[warp][rr][cc]+bias[gc]);
      }
      __syncwarp();
    }
}

// ---------------- fused GATv2 layer 1 (H=4, C=128), online softmax ----------
// block = dst node, warp w = head w, lane handles 4 channels (float4).
__global__ void gat1_fused(const int* __restrict__ ei, const float* __restrict__ att1,
                           const float* __restrict__ bias1){
  int node=blockIdx.x;
  int w=threadIdx.x>>5, lane=threadIdx.x&31;
  float4 xd = ((const float4*)(g_xr1+(size_t)node*512 + w*128))[lane];
  float4 av = ((const float4*)(att1 + w*128))[lane];
  float m=-1e30f, s=0.f;
  float4 acc={0.f,0.f,0.f,0.f};
  int b=g_rowptr[node], en=g_rowptr[node+1];
  for(int i=b;i<en;i++){
    int e=g_elist[i];
    int src = (e<EE)? ei[e] : (e-EE);
    float4 xs = ((const float4*)(g_xl1+(size_t)src*512 + w*128))[lane];
    float v0=xs.x+xd.x; v0 = v0>0.f?v0:0.2f*v0;
    float v1=xs.y+xd.y; v1 = v1>0.f?v1:0.2f*v1;
    float v2=xs.z+xd.z; v2 = v2>0.f?v2:0.2f*v2;
    float v3=xs.w+xd.w; v3 = v3>0.f?v3:0.2f*v3;
    float part = v0*av.x + v1*av.y + v2*av.z + v3*av.w;
    #pragma unroll
    for(int o=16;o;o>>=1) part += __shfl_xor_sync(0xffffffffu,part,o);
    float nm = fmaxf(m, part);
    float sc = __expf(m - nm);
    float p  = __expf(part - nm);
    s = s*sc + p;
    acc.x = acc.x*sc + p*xs.x;
    acc.y = acc.y*sc + p*xs.y;
    acc.z = acc.z*sc + p*xs.z;
    acc.w = acc.w*sc + p*xs.w;
    m = nm;
  }
  float inv = 1.f/s;
  float4 bv = ((const float4*)(bias1 + w*128))[lane];
  float4 o;
  o.x = gelu_t(acc.x*inv + bv.x);
  o.y = gelu_t(acc.y*inv + bv.y);
  o.z = gelu_t(acc.z*inv + bv.z);
  o.w = gelu_t(acc.w*inv + bv.w);
  ((float4*)(g_z1+(size_t)node*512 + w*128))[lane] = o;
}

// ---------------- fused GATv2 layer 2 (H=1, C=128), 4-way split-merge -------
__global__ void gat2_fused(const int* __restrict__ ei, const float* __restrict__ att2,
                           const float* __restrict__ bias2){
  __shared__ float  sm_m[4], sm_s[4];
  __shared__ float4 sm_acc[4][32];
  int node=blockIdx.x;
  int w=threadIdx.x>>5, lane=threadIdx.x&31;
  float4 xd = ((const float4*)(g_xr2+(size_t)node*128))[lane];
  float4 av = ((const float4*)att2)[lane];
  float m=-1e30f, s=0.f;
  float4 acc={0.f,0.f,0.f,0.f};
  int b=g_rowptr[node], en=g_rowptr[node+1];
  for(int i=b+w;i<en;i+=4){
    int e=g_elist[i];
    int src = (e<EE)? ei[e] : (e-EE);
    float4 xs = ((const float4*)(g_xl2+(size_t)src*128))[lane];
    float v0=xs.x+xd.x; v0 = v0>0.f?v0:0.2f*v0;
    float v1=xs.y+xd.y; v1 = v1>0.f?v1:0.2f*v1;
    float v2=xs.z+xd.z; v2 = v2>0.f?v2:0.2f*v2;
    float v3=xs.w+xd.w; v3 = v3>0.f?v3:0.2f*v3;
    float part = v0*av.x + v1*av.y + v2*av.z + v3*av.w;
    #pragma unroll
    for(int o=16;o;o>>=1) part += __shfl_xor_sync(0xffffffffu,part,o);
    float nm = fmaxf(m, part);
    float sc = __expf(m - nm);
    float p  = __expf(part - nm);
    s = s*sc + p;
    acc.x = acc.x*sc + p*xs.x;
    acc.y = acc.y*sc + p*xs.y;
    acc.z = acc.z*sc + p*xs.z;
    acc.w = acc.w*sc + p*xs.w;
    m = nm;
  }
  if(lane==0){ sm_m[w]=m; sm_s[w]=s; }
  sm_acc[w][lane]=acc;
  __syncthreads();
  if(w==0){
    float M = fmaxf(fmaxf(sm_m[0],sm_m[1]),fmaxf(sm_m[2],sm_m[3]));
    float S=0.f;
    float4 o={0.f,0.f,0.f,0.f};
    #pragma unroll
    for(int ww=0;ww<4;ww++){
      float sc=__expf(sm_m[ww]-M);
      S += sm_s[ww]*sc;
      float4 a=sm_acc[ww][lane];
      o.x+=a.x*sc; o.y+=a.y*sc; o.z+=a.z*sc; o.w+=a.w*sc;
    }
    float inv=1.f/S;
    float4 bv=((const float4*)bias2)[lane];
    float4 r;
    r.x=o.x*inv+bv.x; r.y=o.y*inv+bv.y; r.z=o.z*inv+bv.z; r.w=o.w*inv+bv.w;
    ((float4*)(g_z2+(size_t)node*128))[lane]=r;
  }
}

// ---------------- decoder output: out[e] = h[e] . Wd2 + b2 -------------------
__global__ void dec_out_kernel(const float* __restrict__ Wd2, const float* __restrict__ bd2,
                               float* __restrict__ out){
  int warp=threadIdx.x>>5, lane=threadIdx.x&31;
  int e=blockIdx.x*8+warp;
  if(e>=ELN) return;
  const float* h=g_h+(size_t)e*128;
  float acc=0.f;
  #pragma unroll
  for(int i=0;i<4;i++){
    int c=lane+32*i;
    acc += h[c]*Wd2[c];
  }
  #pragma unroll
  for(int o=16;o;o>>=1) acc+=__shfl_xor_sync(0xffffffffu,acc,o);
  if(lane==0) out[e]=acc+bd2[0];
}

// ---------------- launch -----------------------------------------------------
extern "C" void kernel_launch(void* const* d_in, const int* in_sizes, int n_in,
                              void* d_out, int out_size){
  const float* x    =(const float*)d_in[0];
  const int*   ei   =(const int*  )d_in[1];
  const int*   eli  =(const int*  )d_in[2];
  const float* Wl1  =(const float*)d_in[3];
  const float* bl1  =(const float*)d_in[4];
  const float* Wr1  =(const float*)d_in[5];
  const float* br1  =(const float*)d_in[6];
  const float* att1 =(const float*)d_in[7];
  const float* bias1=(const float*)d_in[8];
  const float* Wl2  =(const float*)d_in[9];
  const float* bl2  =(const float*)d_in[10];
  const float* Wr2  =(const float*)d_in[11];
  const float* br2  =(const float*)d_in[12];
  const float* att2 =(const float*)d_in[13];
  const float* bias2=(const float*)d_in[14];
  const float* Wd1  =(const float*)d_in[15];
  const float* bd1  =(const float*)d_in[16];
  const float* Wd2  =(const float*)d_in[17];
  const float* bd2  =(const float*)d_in[18];
  float* out=(float*)d_out;

  float *p_xl1,*p_xr1,*p_z1,*p_xl2,*p_xr2;
  cudaGetSymbolAddress((void**)&p_xl1, g_xl1);
  cudaGetSymbolAddress((void**)&p_xr1, g_xr1);
  cudaGetSymbolAddress((void**)&p_z1 , g_z1 );
  cudaGetSymbolAddress((void**)&p_xl2, g_xl2);
  cudaGetSymbolAddress((void**)&p_xr2, g_xr2);

  // CSR build
  init_kernel   <<<(NN+255)/256,256>>>();
  count_kernel  <<<(ETOT+255)/256,256>>>(ei);
  scan_kernel   <<<1,1024>>>();
  scatter_kernel<<<(ETOT+255)/256,256>>>(ei);

  // layer-1 node transforms: xl1 = x@Wl1+bl1, xr1 = x@Wr1+br1 (shared A)
  wmma_gemm2<<<dim3(512/128,(NN+127)/128,2),256>>>(x, Wl1, bl1, p_xl1, Wr1, br1, p_xr1,
                                                   NN, 256, 512);
  // layer-1 fused attention (online softmax + aggregate + gelu)
  gat1_fused<<<NN,128>>>(ei, att1, bias1);

  // layer-2 node transforms
  wmma_gemm2<<<dim3(1,(NN+127)/128,2),256>>>(p_z1, Wl2, bl2, p_xl2, Wr2, br2, p_xr2,
                                             NN, 512, 128);
  // layer-2 fused attention
  gat2_fused<<<NN,128>>>(ei, att2, bias2);

  // decoder: gather-fused GEMM + gelu, then 128-dot
  wmma_gemm_dec<<<dim3(1,(ELN+127)/128),256>>>(eli, Wd1, bd1);
  dec_out_kernel<<<(ELN+7)/8,256>>>(Wd2, bd2, out);
}

// round 5
// speedup vs baseline: 3.1122x; 1.2527x over previous
#include <cuda_runtime.h>
#include <mma.h>
#include <math.h>

using namespace nvcuda;

#define NN 20000
#define EE 320000
#define ETOT 340000      // EE + NN self loops
#define ELN 100000

// ---------------- scratch (device globals; no allocation allowed) ----------
__device__ float g_xl1[NN*512];
__device__ float g_xr1[NN*512];
__device__ float g_z1 [NN*512];
__device__ float g_xl2[NN*128];
__device__ float g_xr2[NN*128];
__device__ float g_z2 [NN*128];
__device__ int   g_deg[NN];
__device__ int   g_rowptr[NN+1];
__device__ int   g_cursor[NN];
__device__ int   g_slist[ETOT];   // src node per CSR slot (dst implicit by row)

__device__ __forceinline__ float gelu_t(float x){
  float u = 0.7978845608028654f*(x + 0.044715f*x*x*x);
  return 0.5f*x*(1.0f+tanhf(u));
}

// ---------------- CSR build --------------------------------------------------
__global__ void init_kernel(){
  int t=blockIdx.x*blockDim.x+threadIdx.x;
  if(t<NN){ g_deg[t]=0; g_cursor[t]=0; }
}

__global__ void count_kernel(const int* __restrict__ ei){
  int e=blockIdx.x*blockDim.x+threadIdx.x;
  if(e>=ETOT)return;
  int dst = (e<EE) ? ei[EE+e] : (e-EE);
  atomicAdd(&g_deg[dst],1);
}

__global__ void scan_kernel(){
  __shared__ int sums[1024];
  int tid=threadIdx.x;
  const int CH=(NN+1023)/1024;           // 20
  int start=tid*CH;
  int s=0;
  for(int i=0;i<CH;i++){int idx=start+i; if(idx<NN) s+=g_deg[idx];}
  sums[tid]=s; __syncthreads();
  for(int off=1;off<1024;off<<=1){
    int v=sums[tid];
    int add=(tid>=off)?sums[tid-off]:0;
    __syncthreads();
    sums[tid]=v+add;
    __syncthreads();
  }
  int run=(tid==0)?0:sums[tid-1];
  for(int i=0;i<CH;i++){
    int idx=start+i;
    if(idx<NN){ g_rowptr[idx]=run; run+=g_deg[idx]; }
  }
  if(tid==0) g_rowptr[NN]=sums[1023];
}

__global__ void scatter_kernel(const int* __restrict__ ei){
  int e=blockIdx.x*blockDim.x+threadIdx.x;
  if(e>=ETOT)return;
  int src,dst;
  if(e<EE){ src=ei[e]; dst=ei[EE+e]; } else { src=e-EE; dst=src; }
  int pos=atomicAdd(&g_cursor[dst],1);
  g_slist[g_rowptr[dst]+pos]=src;
}

// ---------------- TF32 WMMA GEMM (bias fused into accumulator init) ---------
#define BM 128
#define BN 128
#define BK 16

__global__ void wmma_gemm2(const float* __restrict__ A,
                           const float* __restrict__ B1, const float* __restrict__ bias1_,
                           float* __restrict__ C1,
                           const float* __restrict__ B2, const float* __restrict__ bias2_,
                           float* __restrict__ C2,
                           int M, int K, int N){
  const float* B    = blockIdx.z ? B2 : B1;
  const float* bias = blockIdx.z ? bias2_ : bias1_;
  float*       C    = blockIdx.z ? C2 : C1;

  __shared__ float As[BM][BK+4];
  __shared__ float Bs[BK][BN+4];
  __shared__ float BiasR[16][BN+4];

  int tid=threadIdx.x;
  int warp=tid>>5, lane=tid&31;
  int wm=warp>>1, wn=warp&1;
  int row0=blockIdx.y*BM, col0=blockIdx.x*BN;

  // replicate bias tile into 16 rows, then init accumulators from it
  for(int i=tid;i<16*BN;i+=256){ int r=i>>7, c=i&127; BiasR[r][c]=bias[col0+c]; }
  __syncthreads();

  wmma::fragment<wmma::accumulator,16,16,8,float> acc[2][4];
  #pragma unroll
  for(int i=0;i<2;i++)
    #pragma unroll
    for(int j=0;j<4;j++)
      wmma::load_matrix_sync(acc[i][j], &BiasR[0][wn*64+j*16], BN+4, wmma::mem_row_major);
  __syncthreads();

  for(int k0=0;k0<K;k0+=BK){
    #pragma unroll
    for(int it=0;it<2;it++){
      int i=tid+256*it;
      int r=i>>2, c4=(i&3)*4;
      float4 v={0.f,0.f,0.f,0.f};
      int gr=row0+r;
      if(gr<M) v=*(const float4*)&A[(size_t)gr*K + k0 + c4];
      As[r][c4+0]=wmma::__float_to_tf32(v.x);
      As[r][c4+1]=wmma::__float_to_tf32(v.y);
      As[r][c4+2]=wmma::__float_to_tf32(v.z);
      As[r][c4+3]=wmma::__float_to_tf32(v.w);
    }
    #pragma unroll
    for(int it=0;it<2;it++){
      int i=tid+256*it;
      int r=i>>5, c4=(i&31)*4;
      float4 v=*(const float4*)&B[(size_t)(k0+r)*N + col0 + c4];
      Bs[r][c4+0]=wmma::__float_to_tf32(v.x);
      Bs[r][c4+1]=wmma::__float_to_tf32(v.y);
      Bs[r][c4+2]=wmma::__float_to_tf32(v.z);
      Bs[r][c4+3]=wmma::__float_to_tf32(v.w);
    }
    __syncthreads();
    #pragma unroll
    for(int ks=0;ks<BK;ks+=8){
      wmma::fragment<wmma::matrix_a,16,16,8,wmma::precision::tf32,wmma::row_major> af[2];
      wmma::fragment<wmma::matrix_b,16,16,8,wmma::precision::tf32,wmma::row_major> bf[4];
      #pragma unroll
      for(int i=0;i<2;i++) wmma::load_matrix_sync(af[i], &As[wm*32+i*16][ks], BK+4);
      #pragma unroll
      for(int j=0;j<4;j++) wmma::load_matrix_sync(bf[j], &Bs[ks][wn*64+j*16], BN+4);
      #pragma unroll
      for(int i=0;i<2;i++)
        #pragma unroll
        for(int j=0;j<4;j++) wmma::mma_sync(acc[i][j],af[i],bf[j],acc[i][j]);
    }
    __syncthreads();
  }

  if(row0+BM<=M){
    // fast path: direct global store (bias already in acc)
    #pragma unroll
    for(int i=0;i<2;i++)
      #pragma unroll
      for(int j=0;j<4;j++){
        int r0=row0+wm*32+i*16, c0=col0+wn*64+j*16;
        wmma::store_matrix_sync(&C[(size_t)r0*N+c0], acc[i][j], N, wmma::mem_row_major);
      }
  } else {
    // ragged tail: stage via reused As
    float* St = &As[warp*16][0];     // 16x20 per warp
    #pragma unroll
    for(int i=0;i<2;i++)
      #pragma unroll
      for(int j=0;j<4;j++){
        wmma::store_matrix_sync(St, acc[i][j], 20, wmma::mem_row_major);
        __syncwarp();
        int r0=row0+wm*32+i*16, c0=col0+wn*64+j*16;
        #pragma unroll
        for(int t=lane;t<256;t+=32){
          int rr=t>>4, cc=t&15;
          int gr=r0+rr;
          if(gr<M) C[(size_t)gr*N+c0+cc]=St[rr*20+cc];
        }
        __syncwarp();
      }
  }
}

// Decoder fully fused: out[r] = dot( gelu( cat(z2[eli0[r]],z2[eli1[r]]) @ Wd1 + bd1 ), Wd2 ) + bd2
__global__ void wmma_gemm_dec(const int* __restrict__ eli,
                              const float* __restrict__ B,    // Wd1 [256x128]
                              const float* __restrict__ bias, // bd1 [128]
                              const float* __restrict__ Wd2,  // [128]
                              const float* __restrict__ bd2,  // [1]
                              float* __restrict__ out){
  const int K=256, N=128;
  __shared__ float As[BM][BK+4];
  __shared__ float Bs[BK][BN+4];
  __shared__ float St[8][16][20];
  __shared__ float rowsum[128];
  __shared__ float w2s[128];
  __shared__ float bias_s[128];

  int tid=threadIdx.x;
  int warp=tid>>5, lane=tid&31;
  int wm=warp>>1, wn=warp&1;
  int row0=blockIdx.y*BM;

  if(tid<128){ rowsum[tid]=0.f; w2s[tid]=Wd2[tid]; bias_s[tid]=bias[tid]; }

  wmma::fragment<wmma::accumulator,16,16,8,float> acc[2][4];
  #pragma unroll
  for(int i=0;i<2;i++)
    #pragma unroll
    for(int j=0;j<4;j++) wmma::fill_fragment(acc[i][j],0.f);

  for(int k0=0;k0<K;k0+=BK){
    const int* idxp = (k0<128) ? eli : (eli+ELN);
    int koff = (k0<128) ? k0 : (k0-128);
    #pragma unroll
    for(int it=0;it<2;it++){
      int i=tid+256*it;
      int r=i>>2, c4=(i&3)*4;
      float4 v={0.f,0.f,0.f,0.f};
      int gr=row0+r;
      if(gr<ELN){
        int node=idxp[gr];
        v=*(const float4*)&g_z2[(size_t)node*128 + koff + c4];
      }
      As[r][c4+0]=wmma::__float_to_tf32(v.x);
      As[r][c4+1]=wmma::__float_to_tf32(v.y);
      As[r][c4+2]=wmma::__float_to_tf32(v.z);
      As[r][c4+3]=wmma::__float_to_tf32(v.w);
    }
    #pragma unroll
    for(int it=0;it<2;it++){
      int i=tid+256*it;
      int r=i>>5, c4=(i&31)*4;
      float4 v=*(const float4*)&B[(size_t)(k0+r)*N + c4];
      Bs[r][c4+0]=wmma::__float_to_tf32(v.x);
      Bs[r][c4+1]=wmma::__float_to_tf32(v.y);
      Bs[r][c4+2]=wmma::__float_to_tf32(v.z);
      Bs[r][c4+3]=wmma::__float_to_tf32(v.w);
    }
    __syncthreads();
    #pragma unroll
    for(int ks=0;ks<BK;ks+=8){
      wmma::fragment<wmma::matrix_a,16,16,8,wmma::precision::tf32,wmma::row_major> af[2];
      wmma::fragment<wmma::matrix_b,16,16,8,wmma::precision::tf32,wmma::row_major> bf[4];
      #pragma unroll
      for(int i=0;i<2;i++) wmma::load_matrix_sync(af[i], &As[wm*32+i*16][ks], BK+4);
      #pragma unroll
      for(int j=0;j<4;j++) wmma::load_matrix_sync(bf[j], &Bs[ks][wn*64+j*16], BN+4);
      #pragma unroll
      for(int i=0;i<2;i++)
        #pragma unroll
        for(int j=0;j<4;j++) wmma::mma_sync(acc[i][j],af[i],bf[j],acc[i][j]);
    }
    __syncthreads();
  }

  // epilogue: gelu(acc+bias) dotted with Wd2, per-row reduction
  float rowpart=0.f;               // lane owns local row wm*32+lane
  int li = lane>>4;                // which 16-row tile this lane belongs to
  int rr = lane&15;
  #pragma unroll
  for(int i=0;i<2;i++)
    #pragma unroll
    for(int j=0;j<4;j++){
      wmma::store_matrix_sync(&St[warp][0][0], acc[i][j], 20, wmma::mem_row_major);
      __syncwarp();
      if(li==i){
        int c0=wn*64+j*16;
        #pragma unroll
        for(int cc=0;cc<16;cc++){
          int gc=c0+cc;
          rowpart += gelu_t(St[warp][rr][cc]+bias_s[gc])*w2s[gc];
        }
      }
      __syncwarp();
    }
  atomicAdd(&rowsum[wm*32+lane], rowpart);
  __syncthreads();
  if(tid<128){
    int gr=row0+tid;
    if(gr<ELN) out[gr]=rowsum[tid]+bd2[0];
  }
}

// ---------------- fused GATv2 layer 1 (H=4, C=128), 2-stream online softmax --
__global__ void gat1_fused(const float* __restrict__ att1, const float* __restrict__ bias1){
  int node=blockIdx.x;
  int w=threadIdx.x>>5, lane=threadIdx.x&31;
  float4 xd = ((const float4*)(g_xr1+(size_t)node*512 + w*128))[lane];
  float4 av = ((const float4*)(att1 + w*128))[lane];
  float m0=-1e30f, s0=0.f, m1=-1e30f, s1=0.f;
  float4 a0={0.f,0.f,0.f,0.f}, a1={0.f,0.f,0.f,0.f};
  int b=g_rowptr[node], en=g_rowptr[node+1];
  int i=b;
  for(; i+1<en; i+=2){
    int src0=g_slist[i], src1=g_slist[i+1];
    float4 x0 = ((const float4*)(g_xl1+(size_t)src0*512 + w*128))[lane];
    float4 x1 = ((const float4*)(g_xl1+(size_t)src1*512 + w*128))[lane];
    float u,p0,p1;
    u=x0.x+xd.x; u=u>0.f?u:0.2f*u; p0 =u*av.x;
    u=x0.y+xd.y; u=u>0.f?u:0.2f*u; p0+=u*av.y;
    u=x0.z+xd.z; u=u>0.f?u:0.2f*u; p0+=u*av.z;
    u=x0.w+xd.w; u=u>0.f?u:0.2f*u; p0+=u*av.w;
    u=x1.x+xd.x; u=u>0.f?u:0.2f*u; p1 =u*av.x;
    u=x1.y+xd.y; u=u>0.f?u:0.2f*u; p1+=u*av.y;
    u=x1.z+xd.z; u=u>0.f?u:0.2f*u; p1+=u*av.z;
    u=x1.w+xd.w; u=u>0.f?u:0.2f*u; p1+=u*av.w;
    #pragma unroll
    for(int o=16;o;o>>=1){
      p0 += __shfl_xor_sync(0xffffffffu,p0,o);
      p1 += __shfl_xor_sync(0xffffffffu,p1,o);
    }
    float nm0=fmaxf(m0,p0), sc0=__expf(m0-nm0), e0=__expf(p0-nm0);
    float nm1=fmaxf(m1,p1), sc1=__expf(m1-nm1), e1=__expf(p1-nm1);
    s0=s0*sc0+e0; s1=s1*sc1+e1;
    a0.x=a0.x*sc0+e0*x0.x; a0.y=a0.y*sc0+e0*x0.y; a0.z=a0.z*sc0+e0*x0.z; a0.w=a0.w*sc0+e0*x0.w;
    a1.x=a1.x*sc1+e1*x1.x; a1.y=a1.y*sc1+e1*x1.y; a1.z=a1.z*sc1+e1*x1.z; a1.w=a1.w*sc1+e1*x1.w;
    m0=nm0; m1=nm1;
  }
  if(i<en){
    int src0=g_slist[i];
    float4 x0 = ((const float4*)(g_xl1+(size_t)src0*512 + w*128))[lane];
    float u,p0;
    u=x0.x+xd.x; u=u>0.f?u:0.2f*u; p0 =u*av.x;
    u=x0.y+xd.y; u=u>0.f?u:0.2f*u; p0+=u*av.y;
    u=x0.z+xd.z; u=u>0.f?u:0.2f*u; p0+=u*av.z;
    u=x0.w+xd.w; u=u>0.f?u:0.2f*u; p0+=u*av.w;
    #pragma unroll
    for(int o=16;o;o>>=1) p0 += __shfl_xor_sync(0xffffffffu,p0,o);
    float nm0=fmaxf(m0,p0), sc0=__expf(m0-nm0), e0=__expf(p0-nm0);
    s0=s0*sc0+e0;
    a0.x=a0.x*sc0+e0*x0.x; a0.y=a0.y*sc0+e0*x0.y; a0.z=a0.z*sc0+e0*x0.z; a0.w=a0.w*sc0+e0*x0.w;
    m0=nm0;
  }
  // merge streams
  float M=fmaxf(m0,m1);
  float c0=__expf(m0-M), c1=__expf(m1-M);
  float S=s0*c0+s1*c1;
  float inv=1.f/S;
  float4 bv = ((const float4*)(bias1 + w*128))[lane];
  float4 o;
  o.x = gelu_t((a0.x*c0+a1.x*c1)*inv + bv.x);
  o.y = gelu_t((a0.y*c0+a1.y*c1)*inv + bv.y);
  o.z = gelu_t((a0.z*c0+a1.z*c1)*inv + bv.z);
  o.w = gelu_t((a0.w*c0+a1.w*c1)*inv + bv.w);
  ((float4*)(g_z1+(size_t)node*512 + w*128))[lane] = o;
}

// ---------------- fused GATv2 layer 2 (H=1, C=128), 4-way split-merge -------
__global__ void gat2_fused(const float* __restrict__ att2, const float* __restrict__ bias2){
  __shared__ float  sm_m[4], sm_s[4];
  __shared__ float4 sm_acc[4][32];
  int node=blockIdx.x;
  int w=threadIdx.x>>5, lane=threadIdx.x&31;
  float4 xd = ((const float4*)(g_xr2+(size_t)node*128))[lane];
  float4 av = ((const float4*)att2)[lane];
  float m=-1e30f, s=0.f;
  float4 acc={0.f,0.f,0.f,0.f};
  int b=g_rowptr[node], en=g_rowptr[node+1];
  for(int i=b+w;i<en;i+=4){
    int src = g_slist[i];
    float4 xs = ((const float4*)(g_xl2+(size_t)src*128))[lane];
    float u,part;
    u=xs.x+xd.x; u=u>0.f?u:0.2f*u; part =u*av.x;
    u=xs.y+xd.y; u=u>0.f?u:0.2f*u; part+=u*av.y;
    u=xs.z+xd.z; u=u>0.f?u:0.2f*u; part+=u*av.z;
    u=xs.w+xd.w; u=u>0.f?u:0.2f*u; part+=u*av.w;
    #pragma unroll
    for(int o=16;o;o>>=1) part += __shfl_xor_sync(0xffffffffu,part,o);
    float nm = fmaxf(m, part);
    float sc = __expf(m - nm);
    float p  = __expf(part - nm);
    s = s*sc + p;
    acc.x = acc.x*sc + p*xs.x;
    acc.y = acc.y*sc + p*xs.y;
    acc.z = acc.z*sc + p*xs.z;
    acc.w = acc.w*sc + p*xs.w;
    m = nm;
  }
  if(lane==0){ sm_m[w]=m; sm_s[w]=s; }
  sm_acc[w][lane]=acc;
  __syncthreads();
  if(w==0){
    float M = fmaxf(fmaxf(sm_m[0],sm_m[1]),fmaxf(sm_m[2],sm_m[3]));
    float S=0.f;
    float4 o={0.f,0.f,0.f,0.f};
    #pragma unroll
    for(int ww=0;ww<4;ww++){
      float sc=__expf(sm_m[ww]-M);
      S += sm_s[ww]*sc;
      float4 a=sm_acc[ww][lane];
      o.x+=a.x*sc; o.y+=a.y*sc; o.z+=a.z*sc; o.w+=a.w*sc;
    }
    float inv=1.f/S;
    float4 bv=((const float4*)bias2)[lane];
    float4 r;
    r.x=o.x*inv+bv.x; r.y=o.y*inv+bv.y; r.z=o.z*inv+bv.z; r.w=o.w*inv+bv.w;
    ((float4*)(g_z2+(size_t)node*128))[lane]=r;
  }
}

// ---------------- launch -----------------------------------------------------
extern "C" void kernel_launch(void* const* d_in, const int* in_sizes, int n_in,
                              void* d_out, int out_size){
  const float* x    =(const float*)d_in[0];
  const int*   ei   =(const int*  )d_in[1];
  const int*   eli  =(const int*  )d_in[2];
  const float* Wl1  =(const float*)d_in[3];
  const float* bl1  =(const float*)d_in[4];
  const float* Wr1  =(const float*)d_in[5];
  const float* br1  =(const float*)d_in[6];
  const float* att1 =(const float*)d_in[7];
  const float* bias1=(const float*)d_in[8];
  const float* Wl2  =(const float*)d_in[9];
  const float* bl2  =(const float*)d_in[10];
  const float* Wr2  =(const float*)d_in[11];
  const float* br2  =(const float*)d_in[12];
  const float* att2 =(const float*)d_in[13];
  const float* bias2=(const float*)d_in[14];
  const float* Wd1  =(const float*)d_in[15];
  const float* bd1  =(const float*)d_in[16];
  const float* Wd2  =(const float*)d_in[17];
  const float* bd2  =(const float*)d_in[18];
  float* out=(float*)d_out;

  float *p_xl1,*p_xr1,*p_z1,*p_xl2,*p_xr2;
  cudaGetSymbolAddress((void**)&p_xl1, g_xl1);
  cudaGetSymbolAddress((void**)&p_xr1, g_xr1);
  cudaGetSymbolAddress((void**)&p_z1 , g_z1 );
  cudaGetSymbolAddress((void**)&p_xl2, g_xl2);
  cudaGetSymbolAddress((void**)&p_xr2, g_xr2);

  // CSR build
  init_kernel   <<<(NN+255)/256,256>>>();
  count_kernel  <<<(ETOT+255)/256,256>>>(ei);
  scan_kernel   <<<1,1024>>>();
  scatter_kernel<<<(ETOT+255)/256,256>>>(ei);

  // layer-1 node transforms: xl1 = x@Wl1+bl1, xr1 = x@Wr1+br1 (shared A)
  wmma_gemm2<<<dim3(512/128,(NN+127)/128,2),256>>>(x, Wl1, bl1, p_xl1, Wr1, br1, p_xr1,
                                                   NN, 256, 512);
  // layer-1 fused attention (online softmax + aggregate + gelu)
  gat1_fused<<<NN,128>>>(att1, bias1);

  // layer-2 node transforms
  wmma_gemm2<<<dim3(1,(NN+127)/128,2),256>>>(p_z1, Wl2, bl2, p_xl2, Wr2, br2, p_xr2,
                                             NN, 512, 128);
  // layer-2 fused attention
  gat2_fused<<<NN,128>>>(att2, bias2);

  // decoder: gather-fused GEMM + gelu + Wd2 dot, all in one kernel
  wmma_gemm_dec<<<dim3(1,(ELN+127)/128),256>>>(eli, Wd1, bd1, Wd2, bd2, out);
}